// round 11
// baseline (speedup 1.0000x reference)
#include <cuda_runtime.h>
#include <cuda_fp16.h>
#include <cstdint>
#include <math.h>

#define B_ 4
#define H_ 16
#define S_ 2048
#define D_ 1024
#define BH 64
#define dh 64
#define NEGV (-1000000.0f)

// ============================ device scratch ============================
__device__ __half g_Yhi[(size_t)BH * S_ * dh];
__device__ __half g_Ylo[(size_t)BH * S_ * dh];
__device__ __half g_XhiT[(size_t)BH * dh * S_];   // [bh][c][s]

// ============================ PTX helpers ============================
__device__ __forceinline__ uint32_t smem_u32(const void* p) {
    uint32_t a;
    asm("{ .reg .u64 t; cvta.to.shared.u64 t, %1; cvt.u32.u64 %0, t; }" : "=r"(a) : "l"(p));
    return a;
}
#define LDSM_X4(r0, r1, r2, r3, addr) \
    asm volatile("ldmatrix.sync.aligned.m8n8.x4.shared.b16 {%0,%1,%2,%3}, [%4];" \
        : "=r"(r0), "=r"(r1), "=r"(r2), "=r"(r3) : "r"(addr))
#define CP_ASYNC16(dst, src) \
    asm volatile("cp.async.cg.shared.global [%0], [%1], 16;" :: "r"(dst), "l"(src))
#define CP_COMMIT() asm volatile("cp.async.commit_group;")
#define CP_WAIT0()  asm volatile("cp.async.wait_group 0;")

__device__ __forceinline__ void mma16816(float d[4], const uint32_t a[4], const uint32_t b[2]) {
    asm volatile(
        "mma.sync.aligned.m16n8k16.row.col.f32.f16.f16.f32 "
        "{%0,%1,%2,%3}, {%4,%5,%6,%7}, {%8,%9}, {%0,%1,%2,%3};"
        : "+f"(d[0]), "+f"(d[1]), "+f"(d[2]), "+f"(d[3])
        : "r"(a[0]), "r"(a[1]), "r"(a[2]), "r"(a[3]), "r"(b[0]), "r"(b[1]));
}
__device__ __forceinline__ uint32_t packh(float a, float b) {
    __half2 h = __floats2half2_rn(a, b);
    return *(uint32_t*)&h;
}
// exp2 of two packed f16 args: returns packed f16x2 result (lo=2^a, hi=2^b)
__device__ __forceinline__ uint32_t ex2_f16x2(float a_lo, float a_hi) {
    uint32_t c, e;
    asm("cvt.rn.f16x2.f32 %0, %1, %2;" : "=r"(c) : "f"(a_hi), "f"(a_lo));
    asm("ex2.approx.f16x2 %0, %1;" : "=r"(e) : "r"(c));
    return e;
}
__device__ __forceinline__ void unpack_h2(uint32_t v, float& lo, float& hi) {
    asm("{.reg .f16 l, h; mov.b32 {l, h}, %2; cvt.f32.f16 %0, l; cvt.f32.f16 %1, h;}"
        : "=f"(lo), "=f"(hi) : "r"(v));
}

// ============================ fused prep (MMA-based, unchanged) ============================
#define PROWB 144
#define PSXL 18432
#define PSWH 36864
#define PSWL 46080
#define PREP_SMEM 55296

__global__ void __launch_bounds__(256, 1) prep_mma(const float* __restrict__ x,
                                                   const float* __restrict__ W,
                                                   const float* __restrict__ bias) {
    extern __shared__ char smem[];
    uint32_t sb = smem_u32(smem);
    int tid = threadIdx.x;
    int w = tid >> 5, l = tid & 31;
    int bh = blockIdx.x >> 4;
    int s0 = (blockIdx.x & 15) * 128;
    int b = bh >> 4, h = bh & 15;

    #pragma unroll
    for (int t = 0; t < 16; t++) {
        int idx = t * 256 + tid;
        int i = idx >> 6, j = idx & 63;
        float v = W[idx];
        __half hi = __float2half_rn(v);
        *(__half*)(smem + PSWH + j * PROWB + i * 2) = hi;
        *(__half*)(smem + PSWL + j * PROWB + i * 2) = __float2half_rn(v - __half2float(hi));
    }

    #pragma unroll
    for (int t = 0; t < 8; t++) {
        int idx = t * 256 + tid;
        int row = idx >> 4, q = idx & 15;
        float4 v = *(const float4*)(x + (size_t)(b * S_ + s0 + row) * D_ + h * 64 + q * 4);
        __half h0 = __float2half_rn(v.x), h1 = __float2half_rn(v.y);
        __half h2 = __float2half_rn(v.z), h3 = __float2half_rn(v.w);
        uint2 hiw = make_uint2(packh(v.x, v.y), packh(v.z, v.w));
        uint2 low = make_uint2(packh(v.x - __half2float(h0), v.y - __half2float(h1)),
                               packh(v.z - __half2float(h2), v.w - __half2float(h3)));
        *(uint2*)(smem + row * PROWB + q * 8) = hiw;
        *(uint2*)(smem + PSXL + row * PROWB + q * 8) = low;
    }
    __syncthreads();

    #pragma unroll
    for (int t = 0; t < 4; t++) {
        int u = t * 256 + tid;
        int c = (u >> 4) & 63;
        int g8 = u & 15;
        uint32_t base = (uint32_t)c * 2;
        uint32_t pk[4];
        #pragma unroll
        for (int p = 0; p < 4; p++) {
            uint16_t a0 = *(const uint16_t*)(smem + base + (g8 * 8 + 2 * p) * PROWB);
            uint16_t a1 = *(const uint16_t*)(smem + base + (g8 * 8 + 2 * p + 1) * PROWB);
            pk[p] = (uint32_t)a0 | ((uint32_t)a1 << 16);
        }
        __half* dst = g_XhiT + ((size_t)bh * 64 + c) * S_ + s0 + g8 * 8;
        *(uint4*)dst = *(uint4*)pk;
    }

    uint32_t ahi[4][4], alo[4][4];
    #pragma unroll
    for (int j = 0; j < 4; j++) {
        uint32_t ad = sb + (uint32_t)(w * 16 + (l & 15)) * PROWB +
                      (uint32_t)(((l >> 4) * 8 + 16 * j) * 2);
        LDSM_X4(ahi[j][0], ahi[j][1], ahi[j][2], ahi[j][3], ad);
        LDSM_X4(alo[j][0], alo[j][1], alo[j][2], alo[j][3], ad + PSXL);
    }

    int R0 = w * 16 + (l >> 2);
    #pragma unroll
    for (int t2 = 0; t2 < 8; t2++) {
        uint32_t b0 = sb + PSWH + (uint32_t)(t2 * 8 + (l & 7)) * PROWB +
                      (uint32_t)(((l >> 3) * 8) * 2);
        uint32_t bh0, bh1, bh2, bh3, bh4, bh5, bh6, bh7;
        uint32_t bl0, bl1, bl2, bl3, bl4, bl5, bl6, bl7;
        LDSM_X4(bh0, bh1, bh2, bh3, b0);
        LDSM_X4(bh4, bh5, bh6, bh7, b0 + 64u);
        LDSM_X4(bl0, bl1, bl2, bl3, b0 + (PSWL - PSWH));
        LDSM_X4(bl4, bl5, bl6, bl7, b0 + (PSWL - PSWH) + 64u);
        uint32_t bhv[8] = {bh0, bh1, bh2, bh3, bh4, bh5, bh6, bh7};
        uint32_t blv[8] = {bl0, bl1, bl2, bl3, bl4, bl5, bl6, bl7};

        float y[4] = {0.0f, 0.0f, 0.0f, 0.0f};
        #pragma unroll
        for (int j = 0; j < 4; j++) {
            mma16816(y, ahi[j], &bhv[2 * j]);
            mma16816(y, alo[j], &bhv[2 * j]);
            mma16816(y, ahi[j], &blv[2 * j]);
        }

        int c = t2 * 8 + (l & 3) * 2;
        float b0f = bias[c], b1f = bias[c + 1];
        y[0] += b0f; y[1] += b1f; y[2] += b0f; y[3] += b1f;

        __half h0 = __float2half_rn(y[0]), h1 = __float2half_rn(y[1]);
        __half h2 = __float2half_rn(y[2]), h3 = __float2half_rn(y[3]);
        size_t o0 = ((size_t)bh * S_ + s0 + R0) * 64 + c;
        size_t o1 = ((size_t)bh * S_ + s0 + R0 + 8) * 64 + c;
        *(uint32_t*)(g_Yhi + o0) = packh(y[0], y[1]);
        *(uint32_t*)(g_Yhi + o1) = packh(y[2], y[3]);
        *(uint32_t*)(g_Ylo + o0) = packh(y[0] - __half2float(h0), y[1] - __half2float(h1));
        *(uint32_t*)(g_Ylo + o1) = packh(y[2] - __half2float(h2), y[3] - __half2float(h3));
    }
}

// ============================ attention kernel ============================
// Round-9 structure; softmax now uses ex2.approx.f16x2: half the MUFU ops,
// no float->half pack (the ex2 output IS the PV A-fragment). Exact fp32
// fl(s/64 + negv) reference rounding and Sterbenz shift preserved.
#define STG 27648
#define ROWB 144
#define LOG2E 1.4426950408889634f

__device__ __forceinline__ void load_stage(uint32_t base, int bh, int kt, int tid) {
    #pragma unroll
    for (int t = 0; t < 6; t++) {
        int tile = t >> 1;                      // 0: Yhi, 1: Ylo, 2: XhiT
        int idx  = ((t & 1) << 8) + tid;        // 0..511
        int n = idx >> 3, o = idx & 7;
        uint32_t dst = base + (uint32_t)tile * 9216u + (uint32_t)n * ROWB + (uint32_t)o * 16u;
        const __half* src;
        if (tile == 0)      src = g_Yhi  + ((size_t)bh * S_ + kt * 64 + n) * 64 + o * 8;
        else if (tile == 1) src = g_Ylo  + ((size_t)bh * S_ + kt * 64 + n) * 64 + o * 8;
        else                src = g_XhiT + ((size_t)bh * 64 + n) * S_ + kt * 64 + o * 8;
        CP_ASYNC16(dst, src);
    }
    CP_COMMIT();
}

__global__ void __launch_bounds__(256, 1) attn_mma(const int* __restrict__ mask,
                                                   float* __restrict__ out) {
    extern __shared__ char smem[];
    uint32_t sb = smem_u32(smem);
    int tid = threadIdx.x;
    int w = tid >> 5, l = tid & 31;
    int bh = blockIdx.y, b = bh >> 4;
    int q0 = blockIdx.x * 128;

    // ---- Yq (hi/lo) into [0, 36864) via cp.async ----
    #pragma unroll
    for (int t = 0; t < 8; t++) {
        int sel = t >> 2;
        int ii  = ((t & 3) << 8) + tid;
        int row = ii >> 3, o = ii & 7;
        uint32_t dst = sb + (uint32_t)sel * 18432u + (uint32_t)row * ROWB + (uint32_t)o * 16u;
        const __half* src = (sel ? g_Ylo : g_Yhi) + ((size_t)bh * S_ + q0 + row) * 64 + o * 8;
        CP_ASYNC16(dst, src);
    }
    CP_COMMIT();
    CP_WAIT0();
    __syncthreads();

    // ---- extract Yq A-fragments ----
    uint32_t ahi[4][4], alo[4][4];
    #pragma unroll
    for (int j = 0; j < 4; j++) {
        uint32_t ad = sb + (uint32_t)(w * 16 + (l & 15)) * ROWB +
                      (uint32_t)(((l >> 4) * 8 + 16 * j) * 2);
        LDSM_X4(ahi[j][0], ahi[j][1], ahi[j][2], ahi[j][3], ad);
        LDSM_X4(alo[j][0], alo[j][1], alo[j][2], alo[j][3], ad + 18432u);
    }
    __syncthreads();

    // ---- prefetch ktile 0 into stage1 ----
    load_stage(sb + STG, bh, 0, tid);
    CP_WAIT0();
    __syncthreads();

    int R0 = q0 + w * 16 + (l >> 2);
    float negv0 = (1.0f - (float)mask[(size_t)b * S_ + R0]) * NEGV;
    float negv1 = (1.0f - (float)mask[(size_t)b * S_ + R0 + 8]) * NEGV;

    float pv[8][4];
    #pragma unroll
    for (int t = 0; t < 8; t++)
        #pragma unroll
        for (int q = 0; q < 4; q++) pv[t][q] = 0.0f;
    float l0 = 0.0f, l1 = 0.0f;

    for (int kt = 0; kt < 32; kt++) {
        uint32_t cur = sb + (uint32_t)((kt + 1) & 1) * STG;
        if (kt < 31) load_stage(sb + (uint32_t)(kt & 1) * STG, bh, kt + 1, tid);

        #pragma unroll
        for (int half = 0; half < 2; half++) {
            uint32_t pA[2][4];   // P for this half's 32 keys (packed f16x2)

            // ---- scores (3-term) + f16x2 softmax ----
            #pragma unroll
            for (int tt = 0; tt < 4; tt++) {
                int t = half * 4 + tt;
                uint32_t b0 = cur + (uint32_t)(t * 8 + (l & 7)) * ROWB +
                              (uint32_t)(((l >> 3) * 8) * 2);
                uint32_t bh0, bh1, bh2, bh3, bh4, bh5, bh6, bh7;
                uint32_t bl0, bl1, bl2, bl3, bl4, bl5, bl6, bl7;
                LDSM_X4(bh0, bh1, bh2, bh3, b0);
                LDSM_X4(bh4, bh5, bh6, bh7, b0 + 64u);
                LDSM_X4(bl0, bl1, bl2, bl3, b0 + 9216u);
                LDSM_X4(bl4, bl5, bl6, bl7, b0 + 9216u + 64u);
                uint32_t bhv[8] = {bh0, bh1, bh2, bh3, bh4, bh5, bh6, bh7};
                uint32_t blv[8] = {bl0, bl1, bl2, bl3, bl4, bl5, bl6, bl7};

                float s[4] = {0.0f, 0.0f, 0.0f, 0.0f};
                #pragma unroll
                for (int j = 0; j < 4; j++) {
                    mma16816(s, ahi[j], &bhv[2 * j]);
                    mma16816(s, alo[j], &bhv[2 * j]);
                    mma16816(s, ahi[j], &blv[2 * j]);
                }

                // exact reference rounding: fl(s/64 + negv); exact shift back
                float lg0 = __fadd_rn(__fmul_rn(s[0], 0.015625f), negv0);
                float lg1 = __fadd_rn(__fmul_rn(s[1], 0.015625f), negv0);
                float lg2 = __fadd_rn(__fmul_rn(s[2], 0.015625f), negv1);
                float lg3 = __fadd_rn(__fmul_rn(s[3], 0.015625f), negv1);
                // exp via f16x2 ex2: output is directly the packed PV A-frag
                uint32_t e01 = ex2_f16x2((lg0 - negv0) * LOG2E, (lg1 - negv0) * LOG2E);
                uint32_t e23 = ex2_f16x2((lg2 - negv1) * LOG2E, (lg3 - negv1) * LOG2E);
                pA[tt >> 1][(tt & 1) * 2 + 0] = e01;
                pA[tt >> 1][(tt & 1) * 2 + 1] = e23;

                float f0, f1, f2, f3;
                unpack_h2(e01, f0, f1);
                unpack_h2(e23, f2, f3);
                l0 += f0 + f1;
                l1 += f2 + f3;
            }

            // ---- PV for this half's 32 keys ----
            #pragma unroll
            for (int t2 = 0; t2 < 8; t2++) {
                uint32_t b0 = cur + 18432u + (uint32_t)(t2 * 8 + (l & 7)) * ROWB +
                              (uint32_t)(((l >> 3) * 8) * 2) + (uint32_t)half * 64u;
                uint32_t bhh0, bhh1, bhh2, bhh3;
                LDSM_X4(bhh0, bhh1, bhh2, bhh3, b0);
                uint32_t bhv[4] = {bhh0, bhh1, bhh2, bhh3};
                mma16816(pv[t2], pA[0], &bhv[0]);
                mma16816(pv[t2], pA[1], &bhv[2]);
            }
        }

        CP_WAIT0();
        __syncthreads();
    }

    // ---- epilogue ----
    l0 += __shfl_xor_sync(0xffffffffu, l0, 1);
    l0 += __shfl_xor_sync(0xffffffffu, l0, 2);
    l1 += __shfl_xor_sync(0xffffffffu, l1, 1);
    l1 += __shfl_xor_sync(0xffffffffu, l1, 2);
    float i0 = 1.0f / l0, i1 = 1.0f / l1;

    #pragma unroll
    for (int t2 = 0; t2 < 8; t2++) {
        int c = t2 * 8 + (l & 3) * 2;
        float2 v0 = make_float2(pv[t2][0] * i0, pv[t2][1] * i0);
        float2 v1 = make_float2(pv[t2][2] * i1, pv[t2][3] * i1);
        *(float2*)(out + ((size_t)bh * S_ + R0) * 64 + c)     = v0;
        *(float2*)(out + ((size_t)bh * S_ + R0 + 8) * 64 + c) = v1;
    }
}

// ============================ launch ============================
extern "C" void kernel_launch(void* const* d_in, const int* in_sizes, int n_in,
                              void* d_out, int out_size) {
    const float* x    = (const float*)d_in[0];
    const int*   mask = (const int*)d_in[1];
    const float* W    = (const float*)d_in[2];
    const float* bias = (const float*)d_in[3];
    float* out = (float*)d_out;

    cudaFuncSetAttribute(prep_mma, cudaFuncAttributeMaxDynamicSharedMemorySize, PREP_SMEM);
    prep_mma<<<BH * 16, 256, PREP_SMEM>>>(x, W, bias);

    cudaFuncSetAttribute(attn_mma, cudaFuncAttributeMaxDynamicSharedMemorySize, 2 * STG);
    dim3 grid(S_ / 128, BH);
    attn_mma<<<grid, 256, 2 * STG>>>(mask, out);
}

// round 13
// speedup vs baseline: 1.0189x; 1.0189x over previous
#include <cuda_runtime.h>
#include <cuda_fp16.h>
#include <cstdint>
#include <math.h>

#define B_ 4
#define H_ 16
#define S_ 2048
#define D_ 1024
#define BH 64
#define dh 64
#define NEGV (-1000000.0f)

// ============================ device scratch ============================
__device__ __half g_Yhi[(size_t)BH * S_ * dh];
__device__ __half g_Ylo[(size_t)BH * S_ * dh];
__device__ __half g_XhiT[(size_t)BH * dh * S_];   // [bh][c][s]

// ============================ PTX helpers ============================
__device__ __forceinline__ uint32_t smem_u32(const void* p) {
    uint32_t a;
    asm("{ .reg .u64 t; cvta.to.shared.u64 t, %1; cvt.u32.u64 %0, t; }" : "=r"(a) : "l"(p));
    return a;
}
#define LDSM_X4(r0, r1, r2, r3, addr) \
    asm volatile("ldmatrix.sync.aligned.m8n8.x4.shared.b16 {%0,%1,%2,%3}, [%4];" \
        : "=r"(r0), "=r"(r1), "=r"(r2), "=r"(r3) : "r"(addr))
#define LDSM_X2(r0, r1, addr) \
    asm volatile("ldmatrix.sync.aligned.m8n8.x2.shared.b16 {%0,%1}, [%2];" \
        : "=r"(r0), "=r"(r1) : "r"(addr))
#define CP_ASYNC16(dst, src) \
    asm volatile("cp.async.cg.shared.global [%0], [%1], 16;" :: "r"(dst), "l"(src))
#define CP_COMMIT() asm volatile("cp.async.commit_group;")
#define CP_WAIT0()  asm volatile("cp.async.wait_group 0;")

__device__ __forceinline__ void mma16816(float d[4], const uint32_t a[4], const uint32_t b[2]) {
    asm volatile(
        "mma.sync.aligned.m16n8k16.row.col.f32.f16.f16.f32 "
        "{%0,%1,%2,%3}, {%4,%5,%6,%7}, {%8,%9}, {%0,%1,%2,%3};"
        : "+f"(d[0]), "+f"(d[1]), "+f"(d[2]), "+f"(d[3])
        : "r"(a[0]), "r"(a[1]), "r"(a[2]), "r"(a[3]), "r"(b[0]), "r"(b[1]));
}
__device__ __forceinline__ uint32_t packh(float a, float b) {
    __half2 h = __floats2half2_rn(a, b);
    return *(uint32_t*)&h;
}

// ============================ fused prep (MMA-based, unchanged) ============================
#define PROWB 144
#define PSXL 18432
#define PSWH 36864
#define PSWL 46080
#define PREP_SMEM 55296

__global__ void __launch_bounds__(256, 1) prep_mma(const float* __restrict__ x,
                                                   const float* __restrict__ W,
                                                   const float* __restrict__ bias) {
    extern __shared__ char smem[];
    uint32_t sb = smem_u32(smem);
    int tid = threadIdx.x;
    int w = tid >> 5, l = tid & 31;
    int bh = blockIdx.x >> 4;
    int s0 = (blockIdx.x & 15) * 128;
    int b = bh >> 4, h = bh & 15;

    #pragma unroll
    for (int t = 0; t < 16; t++) {
        int idx = t * 256 + tid;
        int i = idx >> 6, j = idx & 63;
        float v = W[idx];
        __half hi = __float2half_rn(v);
        *(__half*)(smem + PSWH + j * PROWB + i * 2) = hi;
        *(__half*)(smem + PSWL + j * PROWB + i * 2) = __float2half_rn(v - __half2float(hi));
    }

    #pragma unroll
    for (int t = 0; t < 8; t++) {
        int idx = t * 256 + tid;
        int row = idx >> 4, q = idx & 15;
        float4 v = *(const float4*)(x + (size_t)(b * S_ + s0 + row) * D_ + h * 64 + q * 4);
        __half h0 = __float2half_rn(v.x), h1 = __float2half_rn(v.y);
        __half h2 = __float2half_rn(v.z), h3 = __float2half_rn(v.w);
        uint2 hiw = make_uint2(packh(v.x, v.y), packh(v.z, v.w));
        uint2 low = make_uint2(packh(v.x - __half2float(h0), v.y - __half2float(h1)),
                               packh(v.z - __half2float(h2), v.w - __half2float(h3)));
        *(uint2*)(smem + row * PROWB + q * 8) = hiw;
        *(uint2*)(smem + PSXL + row * PROWB + q * 8) = low;
    }
    __syncthreads();

    #pragma unroll
    for (int t = 0; t < 4; t++) {
        int u = t * 256 + tid;
        int c = (u >> 4) & 63;
        int g8 = u & 15;
        uint32_t base = (uint32_t)c * 2;
        uint32_t pk[4];
        #pragma unroll
        for (int p = 0; p < 4; p++) {
            uint16_t a0 = *(const uint16_t*)(smem + base + (g8 * 8 + 2 * p) * PROWB);
            uint16_t a1 = *(const uint16_t*)(smem + base + (g8 * 8 + 2 * p + 1) * PROWB);
            pk[p] = (uint32_t)a0 | ((uint32_t)a1 << 16);
        }
        __half* dst = g_XhiT + ((size_t)bh * 64 + c) * S_ + s0 + g8 * 8;
        *(uint4*)dst = *(uint4*)pk;
    }

    uint32_t ahi[4][4], alo[4][4];
    #pragma unroll
    for (int j = 0; j < 4; j++) {
        uint32_t ad = sb + (uint32_t)(w * 16 + (l & 15)) * PROWB +
                      (uint32_t)(((l >> 4) * 8 + 16 * j) * 2);
        LDSM_X4(ahi[j][0], ahi[j][1], ahi[j][2], ahi[j][3], ad);
        LDSM_X4(alo[j][0], alo[j][1], alo[j][2], alo[j][3], ad + PSXL);
    }

    int R0 = w * 16 + (l >> 2);
    #pragma unroll
    for (int t2 = 0; t2 < 8; t2++) {
        uint32_t b0 = sb + PSWH + (uint32_t)(t2 * 8 + (l & 7)) * PROWB +
                      (uint32_t)(((l >> 3) * 8) * 2);
        uint32_t bh0, bh1, bh2, bh3, bh4, bh5, bh6, bh7;
        uint32_t bl0, bl1, bl2, bl3, bl4, bl5, bl6, bl7;
        LDSM_X4(bh0, bh1, bh2, bh3, b0);
        LDSM_X4(bh4, bh5, bh6, bh7, b0 + 64u);
        LDSM_X4(bl0, bl1, bl2, bl3, b0 + (PSWL - PSWH));
        LDSM_X4(bl4, bl5, bl6, bl7, b0 + (PSWL - PSWH) + 64u);
        uint32_t bhv[8] = {bh0, bh1, bh2, bh3, bh4, bh5, bh6, bh7};
        uint32_t blv[8] = {bl0, bl1, bl2, bl3, bl4, bl5, bl6, bl7};

        float y[4] = {0.0f, 0.0f, 0.0f, 0.0f};
        #pragma unroll
        for (int j = 0; j < 4; j++) {
            mma16816(y, ahi[j], &bhv[2 * j]);
            mma16816(y, alo[j], &bhv[2 * j]);
            mma16816(y, ahi[j], &blv[2 * j]);
        }

        int c = t2 * 8 + (l & 3) * 2;
        float b0f = bias[c], b1f = bias[c + 1];
        y[0] += b0f; y[1] += b1f; y[2] += b0f; y[3] += b1f;

        __half h0 = __float2half_rn(y[0]), h1 = __float2half_rn(y[1]);
        __half h2 = __float2half_rn(y[2]), h3 = __float2half_rn(y[3]);
        size_t o0 = ((size_t)bh * S_ + s0 + R0) * 64 + c;
        size_t o1 = ((size_t)bh * S_ + s0 + R0 + 8) * 64 + c;
        *(uint32_t*)(g_Yhi + o0) = packh(y[0], y[1]);
        *(uint32_t*)(g_Yhi + o1) = packh(y[2], y[3]);
        *(uint32_t*)(g_Ylo + o0) = packh(y[0] - __half2float(h0), y[1] - __half2float(h1));
        *(uint32_t*)(g_Ylo + o1) = packh(y[2] - __half2float(h2), y[3] - __half2float(h3));
    }
}

// ============================ attention kernel ============================
// Round-6 numerics. NEW structure: 1-tile software pipeline (scores(t+1)
// issued BEFORE softmax(t), so softmax never waits on the scoreboard) and
// per-pair PV (each 16-key pA chunk feeds its 8 PV MMAs immediately).
#define STG 27648
#define ROWB 144

__device__ __forceinline__ void load_stage(uint32_t base, int bh, int kt, int tid) {
    #pragma unroll
    for (int t = 0; t < 6; t++) {
        int tile = t >> 1;                      // 0: Yhi, 1: Ylo, 2: XhiT
        int idx  = ((t & 1) << 8) + tid;        // 0..511
        int n = idx >> 3, o = idx & 7;
        uint32_t dst = base + (uint32_t)tile * 9216u + (uint32_t)n * ROWB + (uint32_t)o * 16u;
        const __half* src;
        if (tile == 0)      src = g_Yhi  + ((size_t)bh * S_ + kt * 64 + n) * 64 + o * 8;
        else if (tile == 1) src = g_Ylo  + ((size_t)bh * S_ + kt * 64 + n) * 64 + o * 8;
        else                src = g_XhiT + ((size_t)bh * 64 + n) * S_ + kt * 64 + o * 8;
        CP_ASYNC16(dst, src);
    }
    CP_COMMIT();
}

__global__ void __launch_bounds__(256, 1) attn_mma(const int* __restrict__ mask,
                                                   float* __restrict__ out) {
    extern __shared__ char smem[];
    uint32_t sb = smem_u32(smem);
    int tid = threadIdx.x;
    int w = tid >> 5, l = tid & 31;
    int bh = blockIdx.y, b = bh >> 4;
    int q0 = blockIdx.x * 128;

    // ---- Yq (hi/lo) into [0, 36864) via cp.async ----
    #pragma unroll
    for (int t = 0; t < 8; t++) {
        int sel = t >> 2;
        int ii  = ((t & 3) << 8) + tid;
        int row = ii >> 3, o = ii & 7;
        uint32_t dst = sb + (uint32_t)sel * 18432u + (uint32_t)row * ROWB + (uint32_t)o * 16u;
        const __half* src = (sel ? g_Ylo : g_Yhi) + ((size_t)bh * S_ + q0 + row) * 64 + o * 8;
        CP_ASYNC16(dst, src);
    }
    CP_COMMIT();
    CP_WAIT0();
    __syncthreads();

    // ---- extract Yq A-fragments ----
    uint32_t ahi[4][4], alo[4][4];
    #pragma unroll
    for (int j = 0; j < 4; j++) {
        uint32_t ad = sb + (uint32_t)(w * 16 + (l & 15)) * ROWB +
                      (uint32_t)(((l >> 4) * 8 + 16 * j) * 2);
        LDSM_X4(ahi[j][0], ahi[j][1], ahi[j][2], ahi[j][3], ad);
        LDSM_X4(alo[j][0], alo[j][1], alo[j][2], alo[j][3], ad + 18432u);
    }
    __syncthreads();

    // ---- prefetch ktile 0 into stage1 ----
    load_stage(sb + STG, bh, 0, tid);
    CP_WAIT0();
    __syncthreads();

    int R0 = q0 + w * 16 + (l >> 2);
    float negv0 = (1.0f - (float)mask[(size_t)b * S_ + R0]) * NEGV;
    float negv1 = (1.0f - (float)mask[(size_t)b * S_ + R0 + 8]) * NEGV;

    float pv[8][4];
    #pragma unroll
    for (int t = 0; t < 8; t++)
        #pragma unroll
        for (int q = 0; q < 4; q++) pv[t][q] = 0.0f;
    float l0 = 0.0f, l1 = 0.0f;

    uint32_t koff = (uint32_t)(((l >> 3) * 8) * 2);
    uint32_t rsel = (uint32_t)(l & 7) * ROWB;

    for (int kt = 0; kt < 32; kt++) {
        uint32_t cur = sb + (uint32_t)((kt + 1) & 1) * STG;
        if (kt < 31) load_stage(sb + (uint32_t)(kt & 1) * STG, bh, kt + 1, tid);

        // ---- compute scores of tile 0 (pipeline prologue) ----
        float s_cur[4], s_nxt[4];
        {
            uint32_t b0 = cur + rsel + koff;
            uint32_t h0, h1, h2, h3, h4, h5, h6, h7, L0, L1, L2, L3, L4, L5, L6, L7;
            LDSM_X4(h0, h1, h2, h3, b0);
            LDSM_X4(h4, h5, h6, h7, b0 + 64u);
            LDSM_X4(L0, L1, L2, L3, b0 + 9216u);
            LDSM_X4(L4, L5, L6, L7, b0 + 9216u + 64u);
            uint32_t bhv[8] = {h0, h1, h2, h3, h4, h5, h6, h7};
            uint32_t blv[8] = {L0, L1, L2, L3, L4, L5, L6, L7};
            s_cur[0] = s_cur[1] = s_cur[2] = s_cur[3] = 0.0f;
            #pragma unroll
            for (int j = 0; j < 4; j++) {
                mma16816(s_cur, ahi[j], &bhv[2 * j]);
                mma16816(s_cur, alo[j], &bhv[2 * j]);
                mma16816(s_cur, ahi[j], &blv[2 * j]);
            }
        }

        uint32_t pA[4];
        #pragma unroll
        for (int t = 0; t < 8; t++) {
            // ---- issue scores(t+1) BEFORE softmax(t): hides MMA latency ----
            if (t < 7) {
                uint32_t b0 = cur + (uint32_t)((t + 1) * 8) * ROWB + rsel + koff;
                uint32_t h0, h1, h2, h3, h4, h5, h6, h7, L0, L1, L2, L3, L4, L5, L6, L7;
                LDSM_X4(h0, h1, h2, h3, b0);
                LDSM_X4(h4, h5, h6, h7, b0 + 64u);
                LDSM_X4(L0, L1, L2, L3, b0 + 9216u);
                LDSM_X4(L4, L5, L6, L7, b0 + 9216u + 64u);
                uint32_t bhv[8] = {h0, h1, h2, h3, h4, h5, h6, h7};
                uint32_t blv[8] = {L0, L1, L2, L3, L4, L5, L6, L7};
                s_nxt[0] = s_nxt[1] = s_nxt[2] = s_nxt[3] = 0.0f;
                #pragma unroll
                for (int j = 0; j < 4; j++) {
                    mma16816(s_nxt, ahi[j], &bhv[2 * j]);
                    mma16816(s_nxt, alo[j], &bhv[2 * j]);
                    mma16816(s_nxt, ahi[j], &blv[2 * j]);
                }
            }

            // ---- softmax(t): s_cur is one tile old -> no scoreboard wait ----
            float lg0 = __fadd_rn(__fmul_rn(s_cur[0], 0.015625f), negv0);
            float lg1 = __fadd_rn(__fmul_rn(s_cur[1], 0.015625f), negv0);
            float lg2 = __fadd_rn(__fmul_rn(s_cur[2], 0.015625f), negv1);
            float lg3 = __fadd_rn(__fmul_rn(s_cur[3], 0.015625f), negv1);
            float p0 = __expf(lg0 - negv0);
            float p1 = __expf(lg1 - negv0);
            float p2 = __expf(lg2 - negv1);
            float p3 = __expf(lg3 - negv1);
            l0 += p0 + p1;
            l1 += p2 + p3;
            pA[(t & 1) * 2 + 0] = packh(p0, p1);
            pA[(t & 1) * 2 + 1] = packh(p2, p3);

            // ---- pair complete: inject PV MMAs for this 16-key chunk ----
            if (t & 1) {
                int j = t >> 1;
                #pragma unroll
                for (int t2 = 0; t2 < 8; t2++) {
                    uint32_t b0 = cur + 18432u + (uint32_t)(t2 * 8) * ROWB + rsel +
                                  koff + (uint32_t)j * 32u;
                    uint32_t r0, r1;
                    LDSM_X2(r0, r1, b0);
                    uint32_t bb[2] = {r0, r1};
                    mma16816(pv[t2], pA, bb);
                }
            }

            s_cur[0] = s_nxt[0]; s_cur[1] = s_nxt[1];
            s_cur[2] = s_nxt[2]; s_cur[3] = s_nxt[3];
        }

        CP_WAIT0();
        __syncthreads();
    }

    // ---- epilogue ----
    l0 += __shfl_xor_sync(0xffffffffu, l0, 1);
    l0 += __shfl_xor_sync(0xffffffffu, l0, 2);
    l1 += __shfl_xor_sync(0xffffffffu, l1, 1);
    l1 += __shfl_xor_sync(0xffffffffu, l1, 2);
    float i0 = 1.0f / l0, i1 = 1.0f / l1;

    #pragma unroll
    for (int t2 = 0; t2 < 8; t2++) {
        int c = t2 * 8 + (l & 3) * 2;
        float2 v0 = make_float2(pv[t2][0] * i0, pv[t2][1] * i0);
        float2 v1 = make_float2(pv[t2][2] * i1, pv[t2][3] * i1);
        *(float2*)(out + ((size_t)bh * S_ + R0) * 64 + c)     = v0;
        *(float2*)(out + ((size_t)bh * S_ + R0 + 8) * 64 + c) = v1;
    }
}

// ============================ launch ============================
extern "C" void kernel_launch(void* const* d_in, const int* in_sizes, int n_in,
                              void* d_out, int out_size) {
    const float* x    = (const float*)d_in[0];
    const int*   mask = (const int*)d_in[1];
    const float* W    = (const float*)d_in[2];
    const float* bias = (const float*)d_in[3];
    float* out = (float*)d_out;

    cudaFuncSetAttribute(prep_mma, cudaFuncAttributeMaxDynamicSharedMemorySize, PREP_SMEM);
    prep_mma<<<BH * 16, 256, PREP_SMEM>>>(x, W, bias);

    cudaFuncSetAttribute(attn_mma, cudaFuncAttributeMaxDynamicSharedMemorySize, 2 * STG);
    dim3 grid(S_ / 128, BH);
    attn_mma<<<grid, 256, 2 * STG>>>(mask, out);
}

// round 14
// speedup vs baseline: 1.1301x; 1.1092x over previous
#include <cuda_runtime.h>
#include <cuda_fp16.h>
#include <cstdint>
#include <math.h>

#define B_ 4
#define H_ 16
#define S_ 2048
#define D_ 1024
#define BH 64
#define dh 64
#define NEGV (-1000000.0f)

// ============================ device scratch ============================
__device__ __half g_Yhi[(size_t)BH * S_ * dh];
__device__ __half g_Ylo[(size_t)BH * S_ * dh];
__device__ __half g_XhiT[(size_t)BH * dh * S_];   // [bh][c][s]

// ============================ PTX helpers ============================
__device__ __forceinline__ uint32_t smem_u32(const void* p) {
    uint32_t a;
    asm("{ .reg .u64 t; cvta.to.shared.u64 t, %1; cvt.u32.u64 %0, t; }" : "=r"(a) : "l"(p));
    return a;
}
#define LDSM_X4(r0, r1, r2, r3, addr) \
    asm volatile("ldmatrix.sync.aligned.m8n8.x4.shared.b16 {%0,%1,%2,%3}, [%4];" \
        : "=r"(r0), "=r"(r1), "=r"(r2), "=r"(r3) : "r"(addr))
#define CP_ASYNC16(dst, src) \
    asm volatile("cp.async.cg.shared.global [%0], [%1], 16;" :: "r"(dst), "l"(src))
#define CP_COMMIT() asm volatile("cp.async.commit_group;")
#define CP_WAIT0()  asm volatile("cp.async.wait_group 0;")

__device__ __forceinline__ void mma16816(float d[4], const uint32_t a[4], const uint32_t b[2]) {
    asm volatile(
        "mma.sync.aligned.m16n8k16.row.col.f32.f16.f16.f32 "
        "{%0,%1,%2,%3}, {%4,%5,%6,%7}, {%8,%9}, {%0,%1,%2,%3};"
        : "+f"(d[0]), "+f"(d[1]), "+f"(d[2]), "+f"(d[3])
        : "r"(a[0]), "r"(a[1]), "r"(a[2]), "r"(a[3]), "r"(b[0]), "r"(b[1]));
}
__device__ __forceinline__ uint32_t packh(float a, float b) {
    __half2 h = __floats2half2_rn(a, b);
    return *(uint32_t*)&h;
}

// 16B-granule swizzle for the prep x-tiles: kills the 16-way gather conflict.
#define XSW(byte, row) ((uint32_t)(byte) ^ (((((uint32_t)(row)) >> 3) & 7u) << 4))

// ============================ fused prep (MMA-based) ============================
#define PROWB 144
#define PSXL 18432
#define PSWH 36864
#define PSWL 46080
#define PREP_SMEM 55296

__global__ void __launch_bounds__(256, 1) prep_mma(const float* __restrict__ x,
                                                   const float* __restrict__ W,
                                                   const float* __restrict__ bias) {
    extern __shared__ char smem[];
    uint32_t sb = smem_u32(smem);
    int tid = threadIdx.x;
    int w = tid >> 5, l = tid & 31;
    int bh = blockIdx.x >> 4;
    int s0 = (blockIdx.x & 15) * 128;
    int b = bh >> 4, h = bh & 15;

    // ---- W: load coalesced, transpose+split into sWh/sWl (no swizzle) ----
    #pragma unroll
    for (int t = 0; t < 16; t++) {
        int idx = t * 256 + tid;
        int i = idx >> 6, j = idx & 63;
        float v = W[idx];
        __half hi = __float2half_rn(v);
        *(__half*)(smem + PSWH + j * PROWB + i * 2) = hi;
        *(__half*)(smem + PSWL + j * PROWB + i * 2) = __float2half_rn(v - __half2float(hi));
    }

    // ---- x tile: load float4, split, store hi/lo rows (swizzled) ----
    #pragma unroll
    for (int t = 0; t < 8; t++) {
        int idx = t * 256 + tid;
        int row = idx >> 4, q = idx & 15;
        float4 v = *(const float4*)(x + (size_t)(b * S_ + s0 + row) * D_ + h * 64 + q * 4);
        __half h0 = __float2half_rn(v.x), h1 = __float2half_rn(v.y);
        __half h2 = __float2half_rn(v.z), h3 = __float2half_rn(v.w);
        uint2 hiw = make_uint2(packh(v.x, v.y), packh(v.z, v.w));
        uint2 low = make_uint2(packh(v.x - __half2float(h0), v.y - __half2float(h1)),
                               packh(v.z - __half2float(h2), v.w - __half2float(h3)));
        uint32_t off = XSW((uint32_t)row * PROWB + (uint32_t)q * 8, row);
        // q*8 only touches bits [3:0] and [6:3]... 8B granule: swizzle bits [4:6]
        // with 8B stores crossing a 16B granule boundary only at q even/odd pairs
        // inside the same 16B unit — XSW flips bits>=16B so the 8B store stays intact.
        *(uint2*)(smem + off) = hiw;
        *(uint2*)(smem + PSXL + off) = low;
    }
    __syncthreads();

    // ---- X^T (hi only) gather: now at most 2-way conflict ----
    #pragma unroll
    for (int t = 0; t < 4; t++) {
        int u = t * 256 + tid;
        int c = (u >> 4) & 63;
        int g8 = u & 15;
        uint32_t pk[4];
        #pragma unroll
        for (int p = 0; p < 4; p++) {
            int r0 = g8 * 8 + 2 * p, r1 = r0 + 1;
            uint16_t a0 = *(const uint16_t*)(smem + XSW((uint32_t)r0 * PROWB + c * 2, r0));
            uint16_t a1 = *(const uint16_t*)(smem + XSW((uint32_t)r1 * PROWB + c * 2, r1));
            pk[p] = (uint32_t)a0 | ((uint32_t)a1 << 16);
        }
        __half* dst = g_XhiT + ((size_t)bh * 64 + c) * S_ + s0 + g8 * 8;
        *(uint4*)dst = *(uint4*)pk;
    }

    // ---- Y via MMA: A-frag LDSM with swizzled addresses ----
    uint32_t ahi[4][4], alo[4][4];
    #pragma unroll
    for (int j = 0; j < 4; j++) {
        int arow = w * 16 + (l & 15);
        uint32_t off = XSW((uint32_t)arow * PROWB + (uint32_t)(((l >> 4) * 8 + 16 * j) * 2), arow);
        LDSM_X4(ahi[j][0], ahi[j][1], ahi[j][2], ahi[j][3], sb + off);
        LDSM_X4(alo[j][0], alo[j][1], alo[j][2], alo[j][3], sb + PSXL + off);
    }

    int R0 = w * 16 + (l >> 2);
    #pragma unroll
    for (int t2 = 0; t2 < 8; t2++) {
        uint32_t b0 = sb + PSWH + (uint32_t)(t2 * 8 + (l & 7)) * PROWB +
                      (uint32_t)(((l >> 3) * 8) * 2);
        uint32_t bh0, bh1, bh2, bh3, bh4, bh5, bh6, bh7;
        uint32_t bl0, bl1, bl2, bl3, bl4, bl5, bl6, bl7;
        LDSM_X4(bh0, bh1, bh2, bh3, b0);
        LDSM_X4(bh4, bh5, bh6, bh7, b0 + 64u);
        LDSM_X4(bl0, bl1, bl2, bl3, b0 + (PSWL - PSWH));
        LDSM_X4(bl4, bl5, bl6, bl7, b0 + (PSWL - PSWH) + 64u);
        uint32_t bhv[8] = {bh0, bh1, bh2, bh3, bh4, bh5, bh6, bh7};
        uint32_t blv[8] = {bl0, bl1, bl2, bl3, bl4, bl5, bl6, bl7};

        float y[4] = {0.0f, 0.0f, 0.0f, 0.0f};
        #pragma unroll
        for (int j = 0; j < 4; j++) {
            mma16816(y, ahi[j], &bhv[2 * j]);
            mma16816(y, alo[j], &bhv[2 * j]);
            mma16816(y, ahi[j], &blv[2 * j]);
        }

        int c = t2 * 8 + (l & 3) * 2;
        float b0f = bias[c], b1f = bias[c + 1];
        y[0] += b0f; y[1] += b1f; y[2] += b0f; y[3] += b1f;

        __half h0 = __float2half_rn(y[0]), h1 = __float2half_rn(y[1]);
        __half h2 = __float2half_rn(y[2]), h3 = __float2half_rn(y[3]);
        size_t o0 = ((size_t)bh * S_ + s0 + R0) * 64 + c;
        size_t o1 = ((size_t)bh * S_ + s0 + R0 + 8) * 64 + c;
        *(uint32_t*)(g_Yhi + o0) = packh(y[0], y[1]);
        *(uint32_t*)(g_Yhi + o1) = packh(y[2], y[3]);
        *(uint32_t*)(g_Ylo + o0) = packh(y[0] - __half2float(h0), y[1] - __half2float(h1));
        *(uint32_t*)(g_Ylo + o1) = packh(y[2] - __half2float(h2), y[3] - __half2float(h3));
    }
}

// ============================ attention kernel (EXACT round-6 best: 350 us) ============================
#define STG 27648
#define ROWB 144

__device__ __forceinline__ void load_stage(uint32_t base, int bh, int kt, int tid) {
    #pragma unroll
    for (int t = 0; t < 6; t++) {
        int tile = t >> 1;                      // 0: Yhi, 1: Ylo, 2: XhiT
        int idx  = ((t & 1) << 8) + tid;        // 0..511
        int n = idx >> 3, o = idx & 7;
        uint32_t dst = base + (uint32_t)tile * 9216u + (uint32_t)n * ROWB + (uint32_t)o * 16u;
        const __half* src;
        if (tile == 0)      src = g_Yhi  + ((size_t)bh * S_ + kt * 64 + n) * 64 + o * 8;
        else if (tile == 1) src = g_Ylo  + ((size_t)bh * S_ + kt * 64 + n) * 64 + o * 8;
        else                src = g_XhiT + ((size_t)bh * 64 + n) * S_ + kt * 64 + o * 8;
        CP_ASYNC16(dst, src);
    }
    CP_COMMIT();
}

__global__ void __launch_bounds__(256, 1) attn_mma(const int* __restrict__ mask,
                                                   float* __restrict__ out) {
    extern __shared__ char smem[];
    uint32_t sb = smem_u32(smem);
    int tid = threadIdx.x;
    int w = tid >> 5, l = tid & 31;
    int bh = blockIdx.y, b = bh >> 4;
    int q0 = blockIdx.x * 128;

    // ---- Yq (hi/lo) into [0, 36864) via cp.async ----
    #pragma unroll
    for (int t = 0; t < 8; t++) {
        int sel = t >> 2;
        int ii  = ((t & 3) << 8) + tid;
        int row = ii >> 3, o = ii & 7;
        uint32_t dst = sb + (uint32_t)sel * 18432u + (uint32_t)row * ROWB + (uint32_t)o * 16u;
        const __half* src = (sel ? g_Ylo : g_Yhi) + ((size_t)bh * S_ + q0 + row) * 64 + o * 8;
        CP_ASYNC16(dst, src);
    }
    CP_COMMIT();
    CP_WAIT0();
    __syncthreads();

    // ---- extract Yq A-fragments ----
    uint32_t ahi[4][4], alo[4][4];
    #pragma unroll
    for (int j = 0; j < 4; j++) {
        uint32_t ad = sb + (uint32_t)(w * 16 + (l & 15)) * ROWB +
                      (uint32_t)(((l >> 4) * 8 + 16 * j) * 2);
        LDSM_X4(ahi[j][0], ahi[j][1], ahi[j][2], ahi[j][3], ad);
        LDSM_X4(alo[j][0], alo[j][1], alo[j][2], alo[j][3], ad + 18432u);
    }
    __syncthreads();

    // ---- prefetch ktile 0 into stage1 ----
    load_stage(sb + STG, bh, 0, tid);
    CP_WAIT0();
    __syncthreads();

    int R0 = q0 + w * 16 + (l >> 2);
    float negv0 = (1.0f - (float)mask[(size_t)b * S_ + R0]) * NEGV;
    float negv1 = (1.0f - (float)mask[(size_t)b * S_ + R0 + 8]) * NEGV;

    float pv[8][4];
    #pragma unroll
    for (int t = 0; t < 8; t++)
        #pragma unroll
        for (int q = 0; q < 4; q++) pv[t][q] = 0.0f;
    float l0 = 0.0f, l1 = 0.0f;

    uint32_t pAhi[4][4];

    for (int kt = 0; kt < 32; kt++) {
        uint32_t cur = sb + (uint32_t)((kt + 1) & 1) * STG;
        if (kt < 31) load_stage(sb + (uint32_t)(kt & 1) * STG, bh, kt + 1, tid);

        // ---- scores (3-term) + softmax + P-pack ----
        #pragma unroll
        for (int t = 0; t < 8; t++) {
            uint32_t b0 = cur + (uint32_t)(t * 8 + (l & 7)) * ROWB + (uint32_t)(((l >> 3) * 8) * 2);
            uint32_t bh0, bh1, bh2, bh3, bh4, bh5, bh6, bh7;
            uint32_t bl0, bl1, bl2, bl3, bl4, bl5, bl6, bl7;
            LDSM_X4(bh0, bh1, bh2, bh3, b0);
            LDSM_X4(bh4, bh5, bh6, bh7, b0 + 64u);
            LDSM_X4(bl0, bl1, bl2, bl3, b0 + 9216u);
            LDSM_X4(bl4, bl5, bl6, bl7, b0 + 9216u + 64u);
            uint32_t bhv[8] = {bh0, bh1, bh2, bh3, bh4, bh5, bh6, bh7};
            uint32_t blv[8] = {bl0, bl1, bl2, bl3, bl4, bl5, bl6, bl7};

            float s[4] = {0.0f, 0.0f, 0.0f, 0.0f};
            #pragma unroll
            for (int j = 0; j < 4; j++) {
                mma16816(s, ahi[j], &bhv[2 * j]);
                mma16816(s, alo[j], &bhv[2 * j]);
                mma16816(s, ahi[j], &blv[2 * j]);
            }

            float lg0 = __fadd_rn(__fmul_rn(s[0], 0.015625f), negv0);
            float lg1 = __fadd_rn(__fmul_rn(s[1], 0.015625f), negv0);
            float lg2 = __fadd_rn(__fmul_rn(s[2], 0.015625f), negv1);
            float lg3 = __fadd_rn(__fmul_rn(s[3], 0.015625f), negv1);
            float p0 = __expf(lg0 - negv0);
            float p1 = __expf(lg1 - negv0);
            float p2 = __expf(lg2 - negv1);
            float p3 = __expf(lg3 - negv1);
            l0 += p0 + p1;
            l1 += p2 + p3;

            pAhi[t >> 1][(t & 1) * 2 + 0] = packh(p0, p1);
            pAhi[t >> 1][(t & 1) * 2 + 1] = packh(p2, p3);
        }

        // ---- PV (1-term): pv += P_hi . X_hi ----
        #pragma unroll
        for (int t2 = 0; t2 < 8; t2++) {
            uint32_t b0 = cur + 18432u + (uint32_t)(t2 * 8 + (l & 7)) * ROWB +
                          (uint32_t)(((l >> 3) * 8) * 2);
            uint32_t bh0, bh1, bh2, bh3, bh4, bh5, bh6, bh7;
            LDSM_X4(bh0, bh1, bh2, bh3, b0);
            LDSM_X4(bh4, bh5, bh6, bh7, b0 + 64u);
            uint32_t bhv[8] = {bh0, bh1, bh2, bh3, bh4, bh5, bh6, bh7};
            #pragma unroll
            for (int j = 0; j < 4; j++)
                mma16816(pv[t2], pAhi[j], &bhv[2 * j]);
        }

        CP_WAIT0();
        __syncthreads();
    }

    // ---- epilogue ----
    l0 += __shfl_xor_sync(0xffffffffu, l0, 1);
    l0 += __shfl_xor_sync(0xffffffffu, l0, 2);
    l1 += __shfl_xor_sync(0xffffffffu, l1, 1);
    l1 += __shfl_xor_sync(0xffffffffu, l1, 2);
    float i0 = 1.0f / l0, i1 = 1.0f / l1;

    #pragma unroll
    for (int t2 = 0; t2 < 8; t2++) {
        int c = t2 * 8 + (l & 3) * 2;
        float2 v0 = make_float2(pv[t2][0] * i0, pv[t2][1] * i0);
        float2 v1 = make_float2(pv[t2][2] * i1, pv[t2][3] * i1);
        *(float2*)(out + ((size_t)bh * S_ + R0) * 64 + c)     = v0;
        *(float2*)(out + ((size_t)bh * S_ + R0 + 8) * 64 + c) = v1;
    }
}

// ============================ launch ============================
extern "C" void kernel_launch(void* const* d_in, const int* in_sizes, int n_in,
                              void* d_out, int out_size) {
    const float* x    = (const float*)d_in[0];
    const int*   mask = (const int*)d_in[1];
    const float* W    = (const float*)d_in[2];
    const float* bias = (const float*)d_in[3];
    float* out = (float*)d_out;

    cudaFuncSetAttribute(prep_mma, cudaFuncAttributeMaxDynamicSharedMemorySize, PREP_SMEM);
    prep_mma<<<BH * 16, 256, PREP_SMEM>>>(x, W, bias);

    cudaFuncSetAttribute(attn_mma, cudaFuncAttributeMaxDynamicSharedMemorySize, 2 * STG);
    dim3 grid(S_ / 128, BH);
    attn_mma<<<grid, 256, 2 * STG>>>(mask, out);
}

// round 16
// speedup vs baseline: 1.4153x; 1.2524x over previous
#include <cuda_runtime.h>
#include <cuda_fp16.h>
#include <cstdint>
#include <math.h>

#define B_ 4
#define H_ 16
#define S_ 2048
#define D_ 1024
#define BH 64
#define dh 64
#define NEGV (-1000000.0f)

// ============================ device scratch ============================
__device__ __half g_Yhi[(size_t)BH * S_ * dh];
__device__ __half g_Ylo[(size_t)BH * S_ * dh];
__device__ __half g_XhiT[(size_t)BH * dh * S_];   // [bh][c][s]

// ============================ PTX helpers ============================
__device__ __forceinline__ uint32_t smem_u32(const void* p) {
    uint32_t a;
    asm("{ .reg .u64 t; cvta.to.shared.u64 t, %1; cvt.u32.u64 %0, t; }" : "=r"(a) : "l"(p));
    return a;
}
#define LDSM_X4(r0, r1, r2, r3, addr) \
    asm volatile("ldmatrix.sync.aligned.m8n8.x4.shared.b16 {%0,%1,%2,%3}, [%4];" \
        : "=r"(r0), "=r"(r1), "=r"(r2), "=r"(r3) : "r"(addr))
#define CP_ASYNC16(dst, src) \
    asm volatile("cp.async.cg.shared.global [%0], [%1], 16;" :: "r"(dst), "l"(src))
#define CP_COMMIT() asm volatile("cp.async.commit_group;")
#define CP_WAIT0()  asm volatile("cp.async.wait_group 0;")

__device__ __forceinline__ void mma16816(float d[4], const uint32_t a[4], const uint32_t b[2]) {
    asm volatile(
        "mma.sync.aligned.m16n8k16.row.col.f32.f16.f16.f32 "
        "{%0,%1,%2,%3}, {%4,%5,%6,%7}, {%8,%9}, {%0,%1,%2,%3};"
        : "+f"(d[0]), "+f"(d[1]), "+f"(d[2]), "+f"(d[3])
        : "r"(a[0]), "r"(a[1]), "r"(a[2]), "r"(a[3]), "r"(b[0]), "r"(b[1]));
}
__device__ __forceinline__ uint32_t packh(float a, float b) {
    __half2 h = __floats2half2_rn(a, b);
    return *(uint32_t*)&h;
}

// 16B-granule swizzle for the prep x-tiles: kills the 16-way gather conflict.
#define XSW(byte, row) ((uint32_t)(byte) ^ (((((uint32_t)(row)) >> 3) & 7u) << 4))

// ============================ fused prep (round-14 winner, unchanged) ============================
#define PROWB 144
#define PSXL 18432
#define PSWH 36864
#define PSWL 46080
#define PREP_SMEM 55296

__global__ void __launch_bounds__(256, 1) prep_mma(const float* __restrict__ x,
                                                   const float* __restrict__ W,
                                                   const float* __restrict__ bias) {
    extern __shared__ char smem[];
    uint32_t sb = smem_u32(smem);
    int tid = threadIdx.x;
    int w = tid >> 5, l = tid & 31;
    int bh = blockIdx.x >> 4;
    int s0 = (blockIdx.x & 15) * 128;
    int b = bh >> 4, h = bh & 15;

    #pragma unroll
    for (int t = 0; t < 16; t++) {
        int idx = t * 256 + tid;
        int i = idx >> 6, j = idx & 63;
        float v = W[idx];
        __half hi = __float2half_rn(v);
        *(__half*)(smem + PSWH + j * PROWB + i * 2) = hi;
        *(__half*)(smem + PSWL + j * PROWB + i * 2) = __float2half_rn(v - __half2float(hi));
    }

    #pragma unroll
    for (int t = 0; t < 8; t++) {
        int idx = t * 256 + tid;
        int row = idx >> 4, q = idx & 15;
        float4 v = *(const float4*)(x + (size_t)(b * S_ + s0 + row) * D_ + h * 64 + q * 4);
        __half h0 = __float2half_rn(v.x), h1 = __float2half_rn(v.y);
        __half h2 = __float2half_rn(v.z), h3 = __float2half_rn(v.w);
        uint2 hiw = make_uint2(packh(v.x, v.y), packh(v.z, v.w));
        uint2 low = make_uint2(packh(v.x - __half2float(h0), v.y - __half2float(h1)),
                               packh(v.z - __half2float(h2), v.w - __half2float(h3)));
        uint32_t off = XSW((uint32_t)row * PROWB + (uint32_t)q * 8, row);
        *(uint2*)(smem + off) = hiw;
        *(uint2*)(smem + PSXL + off) = low;
    }
    __syncthreads();

    #pragma unroll
    for (int t = 0; t < 4; t++) {
        int u = t * 256 + tid;
        int c = (u >> 4) & 63;
        int g8 = u & 15;
        uint32_t pk[4];
        #pragma unroll
        for (int p = 0; p < 4; p++) {
            int r0 = g8 * 8 + 2 * p, r1 = r0 + 1;
            uint16_t a0 = *(const uint16_t*)(smem + XSW((uint32_t)r0 * PROWB + c * 2, r0));
            uint16_t a1 = *(const uint16_t*)(smem + XSW((uint32_t)r1 * PROWB + c * 2, r1));
            pk[p] = (uint32_t)a0 | ((uint32_t)a1 << 16);
        }
        __half* dst = g_XhiT + ((size_t)bh * 64 + c) * S_ + s0 + g8 * 8;
        *(uint4*)dst = *(uint4*)pk;
    }

    uint32_t ahi[4][4], alo[4][4];
    #pragma unroll
    for (int j = 0; j < 4; j++) {
        int arow = w * 16 + (l & 15);
        uint32_t off = XSW((uint32_t)arow * PROWB + (uint32_t)(((l >> 4) * 8 + 16 * j) * 2), arow);
        LDSM_X4(ahi[j][0], ahi[j][1], ahi[j][2], ahi[j][3], sb + off);
        LDSM_X4(alo[j][0], alo[j][1], alo[j][2], alo[j][3], sb + PSXL + off);
    }

    int R0 = w * 16 + (l >> 2);
    #pragma unroll
    for (int t2 = 0; t2 < 8; t2++) {
        uint32_t b0 = sb + PSWH + (uint32_t)(t2 * 8 + (l & 7)) * PROWB +
                      (uint32_t)(((l >> 3) * 8) * 2);
        uint32_t bh0, bh1, bh2, bh3, bh4, bh5, bh6, bh7;
        uint32_t bl0, bl1, bl2, bl3, bl4, bl5, bl6, bl7;
        LDSM_X4(bh0, bh1, bh2, bh3, b0);
        LDSM_X4(bh4, bh5, bh6, bh7, b0 + 64u);
        LDSM_X4(bl0, bl1, bl2, bl3, b0 + (PSWL - PSWH));
        LDSM_X4(bl4, bl5, bl6, bl7, b0 + (PSWL - PSWH) + 64u);
        uint32_t bhv[8] = {bh0, bh1, bh2, bh3, bh4, bh5, bh6, bh7};
        uint32_t blv[8] = {bl0, bl1, bl2, bl3, bl4, bl5, bl6, bl7};

        float y[4] = {0.0f, 0.0f, 0.0f, 0.0f};
        #pragma unroll
        for (int j = 0; j < 4; j++) {
            mma16816(y, ahi[j], &bhv[2 * j]);
            mma16816(y, alo[j], &bhv[2 * j]);
            mma16816(y, ahi[j], &blv[2 * j]);
        }

        int c = t2 * 8 + (l & 3) * 2;
        float b0f = bias[c], b1f = bias[c + 1];
        y[0] += b0f; y[1] += b1f; y[2] += b0f; y[3] += b1f;

        __half h0 = __float2half_rn(y[0]), h1 = __float2half_rn(y[1]);
        __half h2 = __float2half_rn(y[2]), h3 = __float2half_rn(y[3]);
        size_t o0 = ((size_t)bh * S_ + s0 + R0) * 64 + c;
        size_t o1 = ((size_t)bh * S_ + s0 + R0 + 8) * 64 + c;
        *(uint32_t*)(g_Yhi + o0) = packh(y[0], y[1]);
        *(uint32_t*)(g_Yhi + o1) = packh(y[2], y[3]);
        *(uint32_t*)(g_Ylo + o0) = packh(y[0] - __half2float(h0), y[1] - __half2float(h1));
        *(uint32_t*)(g_Ylo + o1) = packh(y[2] - __half2float(h2), y[3] - __half2float(h3));
    }
}

// ============================ attention kernel ============================
// Round-6 mainloop structure, but scores use 2 terms (Yq_hi + Yq_lo vs K_hi).
// Klo is gone from the pipeline: stage = YKH(9216) + XTH(9216) = 18432 B.
// Yq region [0, 36864) is separate from stages [36864, 73728): no overlap.
#define STG 18432
#define STG_BASE 36864
#define ROWB 144
#define ATTN_SMEM 73728

__device__ __forceinline__ void load_stage(uint32_t base, int bh, int kt, int tid) {
    #pragma unroll
    for (int t = 0; t < 4; t++) {
        int tile = t >> 1;                      // 0: Yhi, 1: XhiT
        int idx  = ((t & 1) << 8) + tid;        // 0..511
        int n = idx >> 3, o = idx & 7;
        uint32_t dst = base + (uint32_t)tile * 9216u + (uint32_t)n * ROWB + (uint32_t)o * 16u;
        const __half* src;
        if (tile == 0) src = g_Yhi  + ((size_t)bh * S_ + kt * 64 + n) * 64 + o * 8;
        else           src = g_XhiT + ((size_t)bh * 64 + n) * S_ + kt * 64 + o * 8;
        CP_ASYNC16(dst, src);
    }
    CP_COMMIT();
}

__global__ void __launch_bounds__(256, 1) attn_mma(const int* __restrict__ mask,
                                                   float* __restrict__ out) {
    extern __shared__ char smem[];
    uint32_t sb = smem_u32(smem);
    int tid = threadIdx.x;
    int w = tid >> 5, l = tid & 31;
    int bh = blockIdx.y, b = bh >> 4;
    int q0 = blockIdx.x * 128;

    // ---- Yq (hi/lo) into [0, 36864) via cp.async ----
    #pragma unroll
    for (int t = 0; t < 8; t++) {
        int sel = t >> 2;
        int ii  = ((t & 3) << 8) + tid;
        int row = ii >> 3, o = ii & 7;
        uint32_t dst = sb + (uint32_t)sel * 18432u + (uint32_t)row * ROWB + (uint32_t)o * 16u;
        const __half* src = (sel ? g_Ylo : g_Yhi) + ((size_t)bh * S_ + q0 + row) * 64 + o * 8;
        CP_ASYNC16(dst, src);
    }
    CP_COMMIT();
    // prefetch ktile 0 into stage1 (no overlap with Yq region)
    load_stage(sb + STG_BASE + STG, bh, 0, tid);
    CP_WAIT0();
    __syncthreads();

    // ---- extract Yq A-fragments ----
    uint32_t ahi[4][4], alo[4][4];
    #pragma unroll
    for (int j = 0; j < 4; j++) {
        uint32_t ad = sb + (uint32_t)(w * 16 + (l & 15)) * ROWB +
                      (uint32_t)(((l >> 4) * 8 + 16 * j) * 2);
        LDSM_X4(ahi[j][0], ahi[j][1], ahi[j][2], ahi[j][3], ad);
        LDSM_X4(alo[j][0], alo[j][1], alo[j][2], alo[j][3], ad + 18432u);
    }

    int R0 = q0 + w * 16 + (l >> 2);
    float negv0 = (1.0f - (float)mask[(size_t)b * S_ + R0]) * NEGV;
    float negv1 = (1.0f - (float)mask[(size_t)b * S_ + R0 + 8]) * NEGV;

    float pv[8][4];
    #pragma unroll
    for (int t = 0; t < 8; t++)
        #pragma unroll
        for (int q = 0; q < 4; q++) pv[t][q] = 0.0f;
    float l0 = 0.0f, l1 = 0.0f;

    uint32_t pAhi[4][4];

    for (int kt = 0; kt < 32; kt++) {
        uint32_t cur = sb + STG_BASE + (uint32_t)((kt + 1) & 1) * STG;
        if (kt < 31) load_stage(sb + STG_BASE + (uint32_t)(kt & 1) * STG, bh, kt + 1, tid);

        // ---- scores (2-term: (Yq_hi + Yq_lo) . K_hi) + softmax + P-pack ----
        #pragma unroll
        for (int t = 0; t < 8; t++) {
            uint32_t b0 = cur + (uint32_t)(t * 8 + (l & 7)) * ROWB + (uint32_t)(((l >> 3) * 8) * 2);
            uint32_t bh0, bh1, bh2, bh3, bh4, bh5, bh6, bh7;
            LDSM_X4(bh0, bh1, bh2, bh3, b0);
            LDSM_X4(bh4, bh5, bh6, bh7, b0 + 64u);
            uint32_t bhv[8] = {bh0, bh1, bh2, bh3, bh4, bh5, bh6, bh7};

            float s[4] = {0.0f, 0.0f, 0.0f, 0.0f};
            #pragma unroll
            for (int j = 0; j < 4; j++) {
                mma16816(s, ahi[j], &bhv[2 * j]);
                mma16816(s, alo[j], &bhv[2 * j]);
            }

            float lg0 = __fadd_rn(__fmul_rn(s[0], 0.015625f), negv0);
            float lg1 = __fadd_rn(__fmul_rn(s[1], 0.015625f), negv0);
            float lg2 = __fadd_rn(__fmul_rn(s[2], 0.015625f), negv1);
            float lg3 = __fadd_rn(__fmul_rn(s[3], 0.015625f), negv1);
            float p0 = __expf(lg0 - negv0);
            float p1 = __expf(lg1 - negv0);
            float p2 = __expf(lg2 - negv1);
            float p3 = __expf(lg3 - negv1);
            l0 += p0 + p1;
            l1 += p2 + p3;

            pAhi[t >> 1][(t & 1) * 2 + 0] = packh(p0, p1);
            pAhi[t >> 1][(t & 1) * 2 + 1] = packh(p2, p3);
        }

        // ---- PV (1-term): pv += P_hi . X_hi ----
        #pragma unroll
        for (int t2 = 0; t2 < 8; t2++) {
            uint32_t b0 = cur + 9216u + (uint32_t)(t2 * 8 + (l & 7)) * ROWB +
                          (uint32_t)(((l >> 3) * 8) * 2);
            uint32_t bh0, bh1, bh2, bh3, bh4, bh5, bh6, bh7;
            LDSM_X4(bh0, bh1, bh2, bh3, b0);
            LDSM_X4(bh4, bh5, bh6, bh7, b0 + 64u);
            uint32_t bhv[8] = {bh0, bh1, bh2, bh3, bh4, bh5, bh6, bh7};
            #pragma unroll
            for (int j = 0; j < 4; j++)
                mma16816(pv[t2], pAhi[j], &bhv[2 * j]);
        }

        CP_WAIT0();
        __syncthreads();
    }

    // ---- epilogue ----
    l0 += __shfl_xor_sync(0xffffffffu, l0, 1);
    l0 += __shfl_xor_sync(0xffffffffu, l0, 2);
    l1 += __shfl_xor_sync(0xffffffffu, l1, 1);
    l1 += __shfl_xor_sync(0xffffffffu, l1, 2);
    float i0 = 1.0f / l0, i1 = 1.0f / l1;

    #pragma unroll
    for (int t2 = 0; t2 < 8; t2++) {
        int c = t2 * 8 + (l & 3) * 2;
        float2 v0 = make_float2(pv[t2][0] * i0, pv[t2][1] * i0);
        float2 v1 = make_float2(pv[t2][2] * i1, pv[t2][3] * i1);
        *(float2*)(out + ((size_t)bh * S_ + R0) * 64 + c)     = v0;
        *(float2*)(out + ((size_t)bh * S_ + R0 + 8) * 64 + c) = v1;
    }
}

// ============================ launch ============================
extern "C" void kernel_launch(void* const* d_in, const int* in_sizes, int n_in,
                              void* d_out, int out_size) {
    const float* x    = (const float*)d_in[0];
    const int*   mask = (const int*)d_in[1];
    const float* W    = (const float*)d_in[2];
    const float* bias = (const float*)d_in[3];
    float* out = (float*)d_out;

    cudaFuncSetAttribute(prep_mma, cudaFuncAttributeMaxDynamicSharedMemorySize, PREP_SMEM);
    prep_mma<<<BH * 16, 256, PREP_SMEM>>>(x, W, bias);

    cudaFuncSetAttribute(attn_mma, cudaFuncAttributeMaxDynamicSharedMemorySize, ATTN_SMEM);
    dim3 grid(S_ / 128, BH);
    attn_mma<<<grid, 256, ATTN_SMEM>>>(mask, out);
}